// round 5
// baseline (speedup 1.0000x reference)
#include <cuda_runtime.h>
#include <math.h>

#define BB 8
#define TT 200
#define UU 50
#define VV 1024

#define FRONT 96
#define RW    369                   // 96 front + 200 data + 73 back; 369%32=17, coprime
#define NROWS (UU + (UU - 1) + 1)   // 50 blank + 49 emit + 1 dummy = 100
#define DMAX  272                   // last step: t=199, col 49 -> 199 + 3*24 + 1

#define INV_LN2 1.4426950408889634f
#define LN2     0.6931471805599453f
#define NEG_INF __int_as_float(0xff800000)
#define SENT    (-1.0e30f)

__device__ __forceinline__ float ex2f(float x) {
    float r; asm("ex2.approx.f32 %0, %1;" : "=f"(r) : "f"(x)); return r;
}
__device__ __forceinline__ float lg2f(float x) {
    float r; asm("lg2.approx.f32 %0, %1;" : "=f"(r) : "f"(x)); return r;
}
__device__ __forceinline__ float logadd2(float x, float y) {
    float e = ex2f(-fabsf(x - y));
    return fmaxf(x, y) + lg2f(1.0f + e);   // finite sentinels: e->0, lg2(1)=0
}

// Scratch: log2-domain normalized log-probs, layout [b][u][t] (packed).
__device__ float g_blank[BB * UU * TT];
__device__ float g_emit [BB * (UU - 1) * TT];

// ---------------------------------------------------------------------------
// Phase 1: one warp per (b,u,column). Warp 0 = blank (v=0), warp 1 = emit.
// ---------------------------------------------------------------------------
__global__ void __launch_bounds__(64)
lse_gather_kernel(const float* __restrict__ h,
                  const int* __restrict__ targets,
                  float* __restrict__ out) {
    int bu = blockIdx.x;
    int b = bu / UU, u = bu % UU;
    int w = threadIdx.x >> 5, lane = threadIdx.x & 31;

    if (bu == 0 && threadIdx.x == 0) *out = 0.0f;

    if (w == 1 && u >= UU - 1) return;
    int v = (w == 1) ? targets[b * (UU - 1) + u] : 0;

    const float* base = h + (size_t)b * TT * UU * VV + (size_t)u * VV + v;

    float x[7];
#pragma unroll
    for (int i = 0; i < 7; ++i) {
        int t = lane + 32 * i;
        x[i] = (t < TT) ? base[(size_t)t * (UU * VV)] * INV_LN2 : NEG_INF;
    }

    float m = x[0];
#pragma unroll
    for (int i = 1; i < 7; ++i) m = fmaxf(m, x[i]);
#pragma unroll
    for (int o = 16; o > 0; o >>= 1) m = fmaxf(m, __shfl_xor_sync(0xffffffffu, m, o));

    float s = 0.0f;
#pragma unroll
    for (int i = 0; i < 7; ++i) s += ex2f(x[i] - m);
#pragma unroll
    for (int o = 16; o > 0; o >>= 1) s += __shfl_xor_sync(0xffffffffu, s, o);

    float lse = m + lg2f(s);

    float* dst = (w == 0) ? (g_blank + (b * UU + u) * TT)
                          : (g_emit  + (b * (UU - 1) + u) * TT);
#pragma unroll
    for (int i = 0; i < 7; ++i) {
        int t = lane + 32 * i;
        if (t < TT) dst[t] = x[i] - lse;
    }
}

// ---------------------------------------------------------------------------
// Phase 2: single-warp wavefront per batch, skewed schedule.
// Lane k owns cols jA=2k (at t = d-3k) and jB=2k+1 (at t = d-3k-1).
//   A needs: own0 (alpha[t-1][jA], reg) and lane k-1's B value from d-2
//            -> shfl issued one iteration early (latency hidden).
//   B needs: own1 (reg) and own0 from d-1 (reg). A,B independent per step.
// Sentinel-padded rows; all operands prefetched one iteration ahead.
// ---------------------------------------------------------------------------
__global__ void __launch_bounds__(256)
rnnt_dp_kernel(const int* __restrict__ input_lens,
               const int* __restrict__ target_lens,
               float* __restrict__ out) {
    extern __shared__ float sm[];
    float* sb    = sm;                         // blank rows [0,50)
    float* se    = sm + UU * RW;               // emit rows  [0,49)
    float* dummy = sm + (UU + UU - 1) * RW;    // all-sentinel row

    int b = blockIdx.x;
    int tid = threadIdx.x;

    for (int i = tid; i < NROWS * RW; i += 256) sm[i] = SENT;
    __syncthreads();
    {
        const float* srcb = g_blank + b * (UU * TT);
        const float* srce = g_emit  + b * ((UU - 1) * TT);
#pragma unroll 4
        for (int i = tid; i < UU * TT; i += 256) {
            int u = i / TT, t = i - u * TT;
            sb[u * RW + FRONT + t] = srcb[i];
        }
#pragma unroll 4
        for (int i = tid; i < (UU - 1) * TT; i += 256) {
            int u = i / TT, t = i - u * TT;
            se[u * RW + FRONT + t] = srce[i];
        }
    }
    __syncthreads();
    if (tid >= 32) return;

    int ti = input_lens[b] - 1;     // >= 99
    int ui = target_lens[b] - 1;    // >= 24

    int k = tid;
    int jA = 2 * k, jB = 2 * k + 1;
    int srcLane = (k + 31) & 31;
    bool actA = (jA < UU), actB = (jB < UU);   // k <= 24

    // Base pointers; element for step d is ptr[d].
    const float* pAb = (actA ? sb + jA * RW       : dummy) + (FRONT - 3 * k - 1); // blank[jA][tA-1]
    const float* pAe = ((k > 0 && actA) ? se + (jA - 1) * RW : dummy) + (FRONT - 3 * k);     // emit[jA-1][tA]
    const float* pBb = (actB ? sb + jB * RW       : dummy) + (FRONT - 3 * k - 2); // blank[jB][tB-1]
    const float* pBe = (actB ? se + (jB - 1) * RW : dummy) + (FRONT - 3 * k - 1); // emit[jB-1][tB]

    // Steps at which this lane produces alpha[ti][ui].
    int dA = (jA == ui) ? ti + 3 * k     : -1;
    int dB = (jB == ui) ? ti + 3 * k + 1 : -1;

    float own0 = (k == 0) ? 0.0f : SENT;   // alpha[0][0] seeded (iter d=0)
    float own1 = SENT;
    float inflight = SENT;                 // neighbor's B value, 2 steps old
    float fin = 0.0f;

    // Prefetch operands for d=1.
    float bA = pAb[1], eA = pAe[1], bB = pBb[1], eB = pBe[1];

#pragma unroll 4
    for (int d = 1; d <= DMAX; ++d) {
        float recvA = inflight;
        inflight = __shfl_sync(0xffffffffu, own1, srcLane);  // consumed at d+1

        float cbA = bA, ceA = eA, cbB = bB, ceB = eB;
        bA = pAb[d + 1]; eA = pAe[d + 1];                    // prefetch d+1
        bB = pBb[d + 1]; eB = pBe[d + 1];

        float xA = own0 + cbA;
        float yA = recvA + ceA;
        float nA = logadd2(xA, yA);

        float xB = own1 + cbB;
        float yB = own0 + ceB;
        float nB = logadd2(xB, yB);

        fin = (d == dA) ? nA : fin;
        fin = (d == dB) ? nB : fin;

        own0 = nA;
        own1 = nB;
    }

    if (jA == ui || jB == ui) {
        float loss2 = fin + sb[ui * RW + FRONT + ti];
        atomicAdd(out, -loss2 * LN2 * (1.0f / BB));
    }
}

// ---------------------------------------------------------------------------
extern "C" void kernel_launch(void* const* d_in, const int* in_sizes, int n_in,
                              void* d_out, int out_size) {
    const float* h           = (const float*)d_in[0];
    const int*   targets     = (const int*)d_in[1];
    const int*   input_lens  = (const int*)d_in[2];
    const int*   target_lens = (const int*)d_in[3];
    float* out = (float*)d_out;

    size_t smem = (size_t)NROWS * RW * sizeof(float);   // 147,600 B
    cudaFuncSetAttribute(rnnt_dp_kernel,
                         cudaFuncAttributeMaxDynamicSharedMemorySize, (int)smem);

    lse_gather_kernel<<<BB * UU, 64>>>(h, targets, out);
    rnnt_dp_kernel<<<BB, 256, smem>>>(input_lens, target_lens, out);
}

// round 6
// speedup vs baseline: 1.0327x; 1.0327x over previous
#include <cuda_runtime.h>
#include <math.h>

#define BB 8
#define TT 200
#define UU 50
#define VV 1024

#define FRONT 64
#define RW    313                   // 64 front + 200 data + 49 back; 313%32=25, coprime
#define NROWS (UU + (UU - 1) + 1)   // 50 blank + 49 emit + 1 dummy = 100
#define NCOLS (UU + UU - 1)         // 99 log-prob columns per batch

#define INV_LN2 1.4426950408889634f
#define LN2     0.6931471805599453f
#define NEG_INF __int_as_float(0xff800000)
#define SENT    (-1.0e30f)

__device__ __forceinline__ float ex2f(float x) {
    float r; asm("ex2.approx.f32 %0, %1;" : "=f"(r) : "f"(x)); return r;
}
__device__ __forceinline__ float lg2f(float x) {
    float r; asm("lg2.approx.f32 %0, %1;" : "=f"(r) : "f"(x)); return r;
}
__device__ __forceinline__ float logadd2(float x, float y) {
    float e = ex2f(-fabsf(x - y));
    return fmaxf(x, y) + lg2f(1.0f + e);   // finite sentinels: e->0, lg2(1)=0
}

// ---------------------------------------------------------------------------
// Fused kernel: one block per batch.
//   Stage A: float4 sentinel fill of the padded smem region.
//   Stage B: all 8 warps compute LSE columns (blank v=0, emit v=targets) and
//            write normalized log2-probs straight into padded smem rows.
//   Stage C: warp 0 runs the R4 wavefront DP (lane k: col k + lagged col 32+k).
// ---------------------------------------------------------------------------
__global__ void __launch_bounds__(256)
rnnt_fused_kernel(const float* __restrict__ h,
                  const int* __restrict__ targets,
                  const int* __restrict__ input_lens,
                  const int* __restrict__ target_lens,
                  float* __restrict__ out) {
    extern __shared__ float sm[];
    float* sb    = sm;                         // blank rows [0,50)
    float* se    = sm + UU * RW;               // emit rows  [0,49)
    float* dummy = sm + (UU + UU - 1) * RW;    // all-sentinel row

    int b   = blockIdx.x;
    int tid = threadIdx.x;
    int w   = tid >> 5, lane = tid & 31;

    // ---- Stage A: sentinel fill (31300 floats = 7825 float4) ----
    {
        float4 sv = make_float4(SENT, SENT, SENT, SENT);
        float4* p = (float4*)sm;
#pragma unroll 4
        for (int i = tid; i < (NROWS * RW) / 4; i += 256) p[i] = sv;
    }
    __syncthreads();

    // ---- Stage B: LSE columns, two per warp-iteration for MLP ----
    const float* hb = h + (size_t)b * TT * UU * VV;

    for (int c = w; c < NCOLS; c += 16) {
        int c2 = c + 8;
        bool has2 = (c2 < NCOLS);

        // column -> (row base, gmem base)
        int u1 = (c  < UU) ? c  : c  - UU;
        int u2 = has2 ? ((c2 < UU) ? c2 : c2 - UU) : 0;
        int v1 = (c  < UU) ? 0 : targets[b * (UU - 1) + u1];
        int v2 = (has2 && c2 >= UU) ? targets[b * (UU - 1) + u2] : 0;
        float* dst1 = ((c  < UU) ? sb + u1 * RW : se + u1 * RW) + FRONT;
        float* dst2 = has2 ? (((c2 < UU) ? sb + u2 * RW : se + u2 * RW) + FRONT) : dummy;

        const float* base1 = hb + (size_t)u1 * VV + v1;
        const float* base2 = hb + (size_t)u2 * VV + v2;

        float x1[7], x2[7];
#pragma unroll
        for (int i = 0; i < 7; ++i) {
            int t = lane + 32 * i;
            bool in = (t < TT);
            x1[i] = in ? base1[(size_t)t * (UU * VV)] * INV_LN2 : NEG_INF;
            x2[i] = (in && has2) ? base2[(size_t)t * (UU * VV)] * INV_LN2 : NEG_INF;
        }

        float m1 = x1[0], m2 = x2[0];
#pragma unroll
        for (int i = 1; i < 7; ++i) { m1 = fmaxf(m1, x1[i]); m2 = fmaxf(m2, x2[i]); }
#pragma unroll
        for (int o = 16; o > 0; o >>= 1) {
            m1 = fmaxf(m1, __shfl_xor_sync(0xffffffffu, m1, o));
            m2 = fmaxf(m2, __shfl_xor_sync(0xffffffffu, m2, o));
        }

        float s1 = 0.0f, s2 = 0.0f;
#pragma unroll
        for (int i = 0; i < 7; ++i) { s1 += ex2f(x1[i] - m1); s2 += ex2f(x2[i] - m2); }
#pragma unroll
        for (int o = 16; o > 0; o >>= 1) {
            s1 += __shfl_xor_sync(0xffffffffu, s1, o);
            s2 += __shfl_xor_sync(0xffffffffu, s2, o);
        }

        float lse1 = m1 + lg2f(s1);
        float lse2 = m2 + lg2f(s2);

#pragma unroll
        for (int i = 0; i < 7; ++i) {
            int t = lane + 32 * i;
            if (t < TT) {
                dst1[t] = x1[i] - lse1;
                if (has2) dst2[t] = x2[i] - lse2;
            }
        }
    }
    __syncthreads();

    // ---- Stage C: wavefront DP (warp 0 only; R4 structure) ----
    if (tid >= 32) return;

    int ti = input_lens[b] - 1;     // >= 99
    int ui = target_lens[b] - 1;    // >= 24

    int k = tid;
    int jB = 32 + k;
    int srcLane = (k + 31) & 31;

    const float* pAb = sb + k * RW + (FRONT - k - 1);                               // blank[k][tA-1]
    const float* pAe = ((k > 0) ? se + (k - 1) * RW : dummy) + (FRONT - k);         // emit[k-1][tA]
    const float* pBb = ((jB < UU) ? sb + jB * RW       : dummy) + (FRONT - k - 33); // blank[jB][tB-1]
    const float* pBe = ((jB < UU) ? se + (jB - 1) * RW : dummy) + (FRONT - k - 32); // emit[jB-1][tB]

    int dA = (k  == ui) ? ti + k      : -1;
    int dB = (jB == ui) ? ti + 32 + k : -1;

    float own0 = (k == 0) ? 0.0f : SENT;   // alpha[0][0] seeded; loop starts d=1
    float own1 = SENT;
    float fin = 0.0f;

#pragma unroll 8
    for (int d = 1; d <= TT + UU - 2; ++d) {
        float prevA = __shfl_sync(0xffffffffu, own0, srcLane);
        float prevB = __shfl_sync(0xffffffffu, own1, srcLane);

        float xA = own0  + pAb[d];
        float yA = prevA + pAe[d];
        float nA = logadd2(xA, yA);

        float xB = own1  + pBb[d];
        float yB = prevB + pBe[d];
        float nB = logadd2(xB, yB);

        fin = (d == dA) ? nA : fin;
        fin = (d == dB) ? nB : fin;

        own0 = nA;
        own1 = (k == 31) ? nA : nB;   // lane 31 mirrors col 31 -> lane 0's prevB
    }

    if ((k == ui) || (jB == ui)) {
        float loss2 = fin + sb[ui * RW + FRONT + ti];
        atomicAdd(out, -loss2 * LN2 * (1.0f / BB));
    }
}

// ---------------------------------------------------------------------------
extern "C" void kernel_launch(void* const* d_in, const int* in_sizes, int n_in,
                              void* d_out, int out_size) {
    const float* h           = (const float*)d_in[0];
    const int*   targets     = (const int*)d_in[1];
    const int*   input_lens  = (const int*)d_in[2];
    const int*   target_lens = (const int*)d_in[3];
    float* out = (float*)d_out;

    size_t smem = (size_t)NROWS * RW * sizeof(float);   // 125,200 B
    cudaFuncSetAttribute(rnnt_fused_kernel,
                         cudaFuncAttributeMaxDynamicSharedMemorySize, (int)smem);

    cudaMemsetAsync(out, 0, sizeof(float));
    rnnt_fused_kernel<<<BB, 256, smem>>>(h, targets, input_lens, target_lens, out);
}

// round 7
// speedup vs baseline: 1.2837x; 1.2430x over previous
#include <cuda_runtime.h>
#include <math.h>

#define BB 8
#define TT 200
#define UU 50
#define VV 1024

#define FRONT 64
#define RW    313                   // 64 front + 200 data + 49 back; 313%32=25, coprime
#define NROWS (UU + (UU - 1) + 1)   // 50 blank + 49 emit + 1 dummy = 100
#define PADSZ (NROWS * RW)          // 31300 floats per batch (125,200 B, 16B-aligned)

#define INV_LN2 1.4426950408889634f
#define LN2     0.6931471805599453f
#define NEG_INF __int_as_float(0xff800000)
#define SENT    (-1.0e30f)

__device__ __forceinline__ float ex2f(float x) {
    float r; asm("ex2.approx.f32 %0, %1;" : "=f"(r) : "f"(x)); return r;
}
__device__ __forceinline__ float lg2f(float x) {
    float r; asm("lg2.approx.f32 %0, %1;" : "=f"(r) : "f"(x)); return r;
}
__device__ __forceinline__ float logadd2(float x, float y) {
    float e = ex2f(-fabsf(x - y));
    return fmaxf(x, y) + lg2f(1.0f + e);   // finite sentinels: e->0, lg2(1)=0
}

// Padded per-batch scratch, written by phase 1 in final smem layout:
// rows 0..49 = blank[u], rows 50..98 = emit[u], row 99 = dummy (all SENT).
__device__ float g_pad[BB * PADSZ];

// ---------------------------------------------------------------------------
// Phase 1: one block per (b,u); warp 0 = blank col (v=0), warp 1 = emit col.
// Writes normalized log2-probs into the padded row + fills that row's pads.
// Warp 1 of u==UU-1 blocks fills the dummy row instead.
// ---------------------------------------------------------------------------
__global__ void __launch_bounds__(64)
lse_gather_kernel(const float* __restrict__ h,
                  const int* __restrict__ targets,
                  float* __restrict__ out) {
    int bu = blockIdx.x;
    int b = bu / UU, u = bu % UU;
    int w = threadIdx.x >> 5, lane = threadIdx.x & 31;

    if (bu == 0 && threadIdx.x == 0) *out = 0.0f;   // safe: phase 2 runs after

    float* batch = g_pad + b * PADSZ;

    if (w == 1 && u >= UU - 1) {
        // fill dummy row with sentinel
        float* dr = batch + (UU + UU - 1) * RW;
        for (int i = lane; i < RW; i += 32) dr[i] = SENT;
        return;
    }

    int v = (w == 1) ? targets[b * (UU - 1) + u] : 0;
    float* row = batch + ((w == 0) ? u : UU + u) * RW;

    // pads
#pragma unroll
    for (int i = lane; i < FRONT; i += 32) row[i] = SENT;
#pragma unroll
    for (int i = FRONT + TT + lane; i < RW; i += 32) row[i] = SENT;

    const float* base = h + (size_t)b * TT * UU * VV + (size_t)u * VV + v;

    float x[7];
#pragma unroll
    for (int i = 0; i < 7; ++i) {
        int t = lane + 32 * i;
        x[i] = (t < TT) ? base[(size_t)t * (UU * VV)] * INV_LN2 : NEG_INF;
    }

    float m = x[0];
#pragma unroll
    for (int i = 1; i < 7; ++i) m = fmaxf(m, x[i]);
#pragma unroll
    for (int o = 16; o > 0; o >>= 1) m = fmaxf(m, __shfl_xor_sync(0xffffffffu, m, o));

    float s = 0.0f;
#pragma unroll
    for (int i = 0; i < 7; ++i) s += ex2f(x[i] - m);
#pragma unroll
    for (int o = 16; o > 0; o >>= 1) s += __shfl_xor_sync(0xffffffffu, s, o);

    float lse = m + lg2f(s);

#pragma unroll
    for (int i = 0; i < 7; ++i) {
        int t = lane + 32 * i;
        if (t < TT) row[FRONT + t] = x[i] - lse;
    }
}

// ---------------------------------------------------------------------------
// Phase 2: flat float4 stage of the padded batch image, then the R4 wavefront
// DP (lane k owns col k and lagged col 32+k) with depth-1 operand prefetch.
// ---------------------------------------------------------------------------
__global__ void __launch_bounds__(256)
rnnt_dp_kernel(const int* __restrict__ input_lens,
               const int* __restrict__ target_lens,
               float* __restrict__ out) {
    extern __shared__ float sm[];
    float* sb    = sm;                         // blank rows [0,50)
    float* se    = sm + UU * RW;               // emit rows  [0,49)
    float* dummy = sm + (UU + UU - 1) * RW;    // all-sentinel row

    int b = blockIdx.x;
    int tid = threadIdx.x;

    // Stage: flat 16B copy, no index math (source already padded+sentineled).
    {
        const float4* src = (const float4*)(g_pad + b * PADSZ);
        float4* dst = (float4*)sm;
#pragma unroll 4
        for (int i = tid; i < PADSZ / 4; i += 256) dst[i] = src[i];
    }
    __syncthreads();
    if (tid >= 32) return;

    int ti = input_lens[b] - 1;     // >= 99
    int ui = target_lens[b] - 1;    // >= 24

    int k = tid;
    int jB = 32 + k;
    int srcLane = (k + 31) & 31;

    const float* pAb = sb + k * RW + (FRONT - k - 1);                               // blank[k][tA-1]
    const float* pAe = ((k > 0) ? se + (k - 1) * RW : dummy) + (FRONT - k);         // emit[k-1][tA]
    const float* pBb = ((jB < UU) ? sb + jB * RW       : dummy) + (FRONT - k - 33); // blank[jB][tB-1]
    const float* pBe = ((jB < UU) ? se + (jB - 1) * RW : dummy) + (FRONT - k - 32); // emit[jB-1][tB]

    int dA = (k  == ui) ? ti + k      : -1;
    int dB = (jB == ui) ? ti + 32 + k : -1;

    float own0 = (k == 0) ? 0.0f : SENT;   // alpha[0][0] seeded; loop starts d=1
    float own1 = SENT;
    float fin = 0.0f;

    // Prefetch operands for d=1.
    float bA = pAb[1], eA = pAe[1], bB = pBb[1], eB = pBe[1];

#pragma unroll 8
    for (int d = 1; d <= TT + UU - 2; ++d) {
        float prevA = __shfl_sync(0xffffffffu, own0, srcLane);
        float prevB = __shfl_sync(0xffffffffu, own1, srcLane);

        float cbA = bA, ceA = eA, cbB = bB, ceB = eB;
        bA = pAb[d + 1]; eA = pAe[d + 1];      // prefetch next step (off-chain);
        bB = pBb[d + 1]; eB = pBe[d + 1];      // final (discarded) read covered by slack

        float xA = own0  + cbA;
        float yA = prevA + ceA;
        float nA = logadd2(xA, yA);

        float xB = own1  + cbB;
        float yB = prevB + ceB;
        float nB = logadd2(xB, yB);

        fin = (d == dA) ? nA : fin;
        fin = (d == dB) ? nB : fin;

        own0 = nA;
        own1 = (k == 31) ? nA : nB;   // lane 31 mirrors col 31 -> lane 0's prevB
    }

    if ((k == ui) || (jB == ui)) {
        float loss2 = fin + sb[ui * RW + FRONT + ti];
        atomicAdd(out, -loss2 * LN2 * (1.0f / BB));
    }
}

// ---------------------------------------------------------------------------
extern "C" void kernel_launch(void* const* d_in, const int* in_sizes, int n_in,
                              void* d_out, int out_size) {
    const float* h           = (const float*)d_in[0];
    const int*   targets     = (const int*)d_in[1];
    const int*   input_lens  = (const int*)d_in[2];
    const int*   target_lens = (const int*)d_in[3];
    float* out = (float*)d_out;

    // +16B slack: the last (discarded) k=0 prefetch reads one element past the
    // dummy row; keep it inside the dynamic smem allocation.
    size_t smem = (size_t)PADSZ * sizeof(float) + 16;
    cudaFuncSetAttribute(rnnt_dp_kernel,
                         cudaFuncAttributeMaxDynamicSharedMemorySize, (int)smem);

    lse_gather_kernel<<<BB * UU, 64>>>(h, targets, out);
    rnnt_dp_kernel<<<BB, 256, smem>>>(input_lens, target_lens, out);
}

// round 8
// speedup vs baseline: 1.5333x; 1.1944x over previous
#include <cuda_runtime.h>
#include <math.h>

#define BB 8
#define TT 200
#define UU 50
#define VV 1024

#define FRONT 64
#define RW    313                   // 64 front + 200 data + 49 back; strides = 23 mod 32 -> conflict-free
#define NROWS (UU + (UU - 1) + 1)   // 50 blank + 49 emit + 1 dummy = 100
#define PADSZ (NROWS * RW)          // 31300 floats per batch
#define MITER 149                   // fused iterations: last = slot B col 49 @ t=198/199

#define INV_LN2 1.4426950408889634f
#define LN2     0.6931471805599453f
#define NEG_INF __int_as_float(0xff800000)
#define SENT    (-1.0e30f)

__device__ __forceinline__ float ex2f(float x) {
    float r; asm("ex2.approx.f32 %0, %1;" : "=f"(r) : "f"(x)); return r;
}
__device__ __forceinline__ float lg2f(float x) {
    float r; asm("lg2.approx.f32 %0, %1;" : "=f"(r) : "f"(x)); return r;
}

// Padded per-batch scratch in final smem layout:
// rows 0..49 = blank[u], rows 50..98 = emit[u], row 99 = dummy (all SENT).
__device__ float g_pad[BB * PADSZ];

// ---------------------------------------------------------------------------
// Phase 1: one block per (b,u); warp 0 = blank col (v=0), warp 1 = emit col.
// Writes normalized log2-probs + row pads. Pokes the DP seed cell.
// ---------------------------------------------------------------------------
__global__ void __launch_bounds__(64)
lse_gather_kernel(const float* __restrict__ h,
                  const int* __restrict__ targets,
                  float* __restrict__ out) {
    int bu = blockIdx.x;
    int b = bu / UU, u = bu % UU;
    int w = threadIdx.x >> 5, lane = threadIdx.x & 31;

    if (bu == 0 && threadIdx.x == 0) *out = 0.0f;   // phase 2 runs after in-stream

    float* batch = g_pad + b * PADSZ;

    if (w == 1 && u >= UU - 1) {
        float* dr = batch + (UU + UU - 1) * RW;     // dummy row
        for (int i = lane; i < RW; i += 32) dr[i] = SENT;
        return;
    }

    int v = (w == 1) ? targets[b * (UU - 1) + u] : 0;
    float* row = batch + ((w == 0) ? u : UU + u) * RW;

#pragma unroll
    for (int i = lane; i < FRONT; i += 32) row[i] = SENT;
#pragma unroll
    for (int i = FRONT + TT + lane; i < RW; i += 32) row[i] = SENT;
    // DP seed: lane 0 slot A's first x-arm reads sb[0][FRONT-1]; 0 here makes
    // alpha[0][0] = 0 fall out of the general recurrence.
    if (w == 0 && u == 0 && lane == 0) row[FRONT - 1] = 0.0f;

    const float* base = h + (size_t)b * TT * UU * VV + (size_t)u * VV + v;

    float x[7];
#pragma unroll
    for (int i = 0; i < 7; ++i) {
        int t = lane + 32 * i;
        x[i] = (t < TT) ? base[(size_t)t * (UU * VV)] * INV_LN2 : NEG_INF;
    }

    float m = x[0];
#pragma unroll
    for (int i = 1; i < 7; ++i) m = fmaxf(m, x[i]);
#pragma unroll
    for (int o = 16; o > 0; o >>= 1) m = fmaxf(m, __shfl_xor_sync(0xffffffffu, m, o));

    float s = 0.0f;
#pragma unroll
    for (int i = 0; i < 7; ++i) s += ex2f(x[i] - m);
#pragma unroll
    for (int o = 16; o > 0; o >>= 1) s += __shfl_xor_sync(0xffffffffu, s, o);

    float lse = m + lg2f(s);

#pragma unroll
    for (int i = 0; i < 7; ++i) {
        int t = lane + 32 * i;
        if (t < TT) row[FRONT + t] = x[i] - lse;
    }
}

// ---------------------------------------------------------------------------
// Phase 2: flat stage, then fused-2 wavefront DP.
// Lane k owns col k (slot A) and col 32+k (slot B, lag 64). Iteration m
// computes TWO cells per slot: t1 = 2m-2k-2 (A) / 2m-2k-66 (B) and t1+1:
//   c1 = logadd(x, y),  x = own+b0, y = nb1+e0
//   c2 = m3 + lg2( ex2(m2+b1-m3)*(1+e) + ex2(z-m3) ),  z = nb2+e1
// Neighbor (c1,c2) pair crosses lanes with one-iteration slack -> shfl cost
// amortized over 2 cells. Sentinel pads make the body branchless.
// ---------------------------------------------------------------------------
__global__ void __launch_bounds__(256)
rnnt_dp_kernel(const int* __restrict__ input_lens,
               const int* __restrict__ target_lens,
               float* __restrict__ out) {
    extern __shared__ float sm[];
    float* sb    = sm;                         // blank rows [0,50)
    float* se    = sm + UU * RW;               // emit rows  [0,49)
    float* dummy = sm + (UU + UU - 1) * RW;    // all-sentinel row

    int b = blockIdx.x;
    int tid = threadIdx.x;

    // Stage: flat 16B copy (source already padded + sentineled).
    {
        const float4* src = (const float4*)(g_pad + b * PADSZ);
        float4* dst = (float4*)sm;
#pragma unroll 4
        for (int i = tid; i < PADSZ / 4; i += 256) dst[i] = src[i];
    }
    __syncthreads();
    if (tid >= 32) return;

    int ti = input_lens[b] - 1;     // >= 99
    int ui = target_lens[b] - 1;    // >= 24

    int k = tid;
    int jB = 32 + k;
    int srcLane = (k + 31) & 31;

    const float* sbA  = sb + k * RW;
    const float* seAn = (k > 0)    ? se + (k - 1) * RW  : dummy;
    const float* sbB  = (jB < UU)  ? sb + jB * RW       : dummy;
    const float* seBn = (k <= 17)  ? se + (jB - 1) * RW : dummy;

    // index [2m]   -> operand at t1 position, [2m+1] -> t1+1 position
    const float* pAb = sbA  + (FRONT - 2 * k - 3);   // blank[k][t1-1], [t1]
    const float* pAe = seAn + (FRONT - 2 * k - 2);   // emit[k-1][t1], [t1+1]
    const float* pBb = sbB  + (FRONT - 2 * k - 67);  // blank[jB][t1B-1], [t1B]
    const float* pBe = seBn + (FRONT - 2 * k - 66);  // emit[jB-1][t1B], [t1B+1]

    bool tiOdd = (ti & 1) != 0;
    int mCapA = (k  == ui) ? (ti >> 1) + k + 1  : -1;
    int mCapB = (jB == ui) ? (ti >> 1) + k + 33 : -1;

    float ownA = (k == 0) ? 0.0f : SENT;   // alpha[-1][0] proxy; seed cell poked in smem
    float ownB = SENT;
    float e1A = SENT, e2A = SENT, e1B = SENT, e2B = SENT;   // exported (c1,c2) pairs
    float fin = 0.0f;

    // Prefetch operands for m=1.
    float bA0 = pAb[2], bA1 = pAb[3], eA0 = pAe[2], eA1 = pAe[3];
    float bB0 = pBb[2], bB1 = pBb[3], eB0 = pBe[2], eB1 = pBe[3];

#pragma unroll 4
    for (int m = 1; m <= MITER; ++m) {
        float nbA1 = __shfl_sync(0xffffffffu, e1A, srcLane);
        float nbA2 = __shfl_sync(0xffffffffu, e2A, srcLane);
        float nbB1 = __shfl_sync(0xffffffffu, e1B, srcLane);
        float nbB2 = __shfl_sync(0xffffffffu, e2B, srcLane);

        float cbA0 = bA0, cbA1 = bA1, ceA0 = eA0, ceA1 = eA1;
        float cbB0 = bB0, cbB1 = bB1, ceB0 = eB0, ceB1 = eB1;
        bA0 = pAb[2 * m + 2]; bA1 = pAb[2 * m + 3];   // prefetch m+1 (off-chain)
        eA0 = pAe[2 * m + 2]; eA1 = pAe[2 * m + 3];
        bB0 = pBb[2 * m + 2]; bB1 = pBb[2 * m + 3];
        eB0 = pBe[2 * m + 2]; eB1 = pBe[2 * m + 3];

        // ---- slot A: cells (t1, k), (t1+1, k) ----
        float xA   = ownA + cbA0;
        float yA   = nbA1 + ceA0;
        float zA   = nbA2 + ceA1;
        float m2A  = fmaxf(xA, yA);
        float eeA  = ex2f(-fabsf(xA - yA));
        float opeA = 1.0f + eeA;
        float c1A  = m2A + lg2f(opeA);
        float m2uA = m2A + cbA1;
        float m3A  = fmaxf(m2uA, zA);
        float sA   = ex2f(m2uA - m3A) * opeA + ex2f(zA - m3A);
        float c2A  = m3A + lg2f(sA);

        // ---- slot B: cells (t1B, jB), (t1B+1, jB) ----
        float xB   = ownB + cbB0;
        float yB   = nbB1 + ceB0;
        float zB   = nbB2 + ceB1;
        float m2B  = fmaxf(xB, yB);
        float eeB  = ex2f(-fabsf(xB - yB));
        float opeB = 1.0f + eeB;
        float c1B  = m2B + lg2f(opeB);
        float m2uB = m2B + cbB1;
        float m3B  = fmaxf(m2uB, zB);
        float sB   = ex2f(m2uB - m3B) * opeB + ex2f(zB - m3B);
        float c2B  = m3B + lg2f(sB);

        float capA = tiOdd ? c2A : c1A;
        float capB = tiOdd ? c2B : c1B;
        fin = (m == mCapA) ? capA : fin;
        fin = (m == mCapB) ? capB : fin;

        ownA = c2A;
        ownB = c2B;
        e1A = c1A; e2A = c2A;
        e1B = (k == 31) ? c1A : c1B;   // lane 31 mirrors slot A -> lane 0's B neighbor = col 31
        e2B = (k == 31) ? c2A : c2B;
    }

    if (mCapA >= 0 || mCapB >= 0) {
        float loss2 = fin + sb[ui * RW + FRONT + ti];
        atomicAdd(out, -loss2 * LN2 * (1.0f / BB));
    }
}

// ---------------------------------------------------------------------------
extern "C" void kernel_launch(void* const* d_in, const int* in_sizes, int n_in,
                              void* d_out, int out_size) {
    const float* h           = (const float*)d_in[0];
    const int*   targets     = (const int*)d_in[1];
    const int*   input_lens  = (const int*)d_in[2];
    const int*   target_lens = (const int*)d_in[3];
    float* out = (float*)d_out;

    // +256B slack: final (discarded) prefetch may read past the dummy row.
    size_t smem = (size_t)PADSZ * sizeof(float) + 256;
    cudaFuncSetAttribute(rnnt_dp_kernel,
                         cudaFuncAttributeMaxDynamicSharedMemorySize, (int)smem);

    lse_gather_kernel<<<BB * UU, 64>>>(h, targets, out);
    rnnt_dp_kernel<<<BB, 256, smem>>>(input_lens, target_lens, out);
}